// round 13
// baseline (speedup 1.0000x reference)
#include <cuda_runtime.h>
#include <cuda_fp16.h>
#include <math.h>
#include <stdint.h>

#define N_F 100000
#define N_H 49152
#define NE  400000
#define TT  12
#define HH  64
#define AHD 128
#define SCANB 98
#define ENCB  ((NE + 255) / 256)
#define FILLB ((NE + 255) / 256)
#define HPB   ((N_H + 3) / 4)
#define PACKB 28                     // 28*1024 = 24576 (Wdec) + 4096 (Wa1)
#define IDXCAP 448

__device__ int     g_deg_se[N_F];
__device__ int     g_deg_de[N_H];
__device__ int     g_deg_sd[N_H];
__device__ int     g_deg_dd[N_F];
__device__ float   g_agg[N_H * TT];
__device__ __half2 g_hp[(size_t)TT * N_H * 32];   // (t, n, h/2)
__device__ int     g_off[N_F + 1];
__device__ int     g_cur[N_F];
__device__ int     g_csr[NE];
__device__ unsigned long long g_lb[SCANB];
__device__ float   g_att[2 * AHD + 2];            // u[128], c2[128], k1, k2
__device__ float   g_ba1[AHD];
__device__ float   g_Wo[HH];
__device__ __align__(16) unsigned g_wdp[TT * 2048];  // packed Wdec fp16 pairs
__device__ __align__(16) unsigned g_wap[4096];       // packed Wa1 fp16 pairs

__device__ __forceinline__ float fast_tanh(float x) {
    float y;
    asm("tanh.approx.f32 %0, %1;" : "=f"(y) : "f"(x));
    return y;
}
__device__ __forceinline__ float nan0(float x) {
    x = (x == x) ? x : 0.f;
    return fminf(fmaxf(x, -3.402823466e38f), 3.402823466e38f);
}
__device__ __forceinline__ float lrelu(float x) { return x > 0.f ? x : 0.01f * x; }
__device__ __forceinline__ unsigned packh2(float a, float b) {
    __half2 h = __floats2half2_rn(a, b);
    return *reinterpret_cast<unsigned*>(&h);
}
__device__ __forceinline__ void mma_f16(float& c0, float& c1, float& c2, float& c3,
                                        unsigned a0, unsigned a1, unsigned a2, unsigned a3,
                                        unsigned b0, unsigned b1) {
    asm("mma.sync.aligned.m16n8k16.row.col.f32.f16.f16.f32 "
        "{%0,%1,%2,%3},{%4,%5,%6,%7},{%8,%9},{%0,%1,%2,%3};"
        : "+f"(c0), "+f"(c1), "+f"(c2), "+f"(c3)
        : "r"(a0), "r"(a1), "r"(a2), "r"(a3), "r"(b0), "r"(b1));
}

// ---------------- launch 0: degrees ----------------
__global__ void k_deg(const int* __restrict__ es, const int* __restrict__ ed,
                      const int* __restrict__ ds, const int* __restrict__ dd) {
    int e = blockIdx.x * blockDim.x + threadIdx.x;
    if (e >= NE) return;
    atomicAdd(&g_deg_se[es[e]], 1);
    atomicAdd(&g_deg_de[ed[e]], 1);
    atomicAdd(&g_deg_sd[ds[e]], 1);
    atomicAdd(&g_deg_dd[dd[e]], 1);
}

// ---------------- launch 1: decoupled-lookback scan + encoder scatter ----------------
__global__ void k_enc_scan(const float* __restrict__ feat, const int* __restrict__ es,
                           const int* __restrict__ ed) {
    int tid = threadIdx.x;
    if (blockIdx.x >= SCANB) {
        int e = (blockIdx.x - SCANB) * 256 + tid;
        if (e >= NE) return;
        int s = es[e], d = ed[e];
        float c = rsqrtf(fmaxf((float)g_deg_se[s], 1.f));
        const float4* fp = reinterpret_cast<const float4*>(feat + (size_t)s * 12);
        float4 v0 = fp[0], v1 = fp[1], v2 = fp[2];
        float vv[12] = {v0.x, v0.y, v0.z, v0.w, v1.x, v1.y, v1.z, v1.w, v2.x, v2.y, v2.z, v2.w};
        float* ap = g_agg + (size_t)d * TT;
#pragma unroll
        for (int t = 0; t < 12; t++) atomicAdd(ap + t, nan0(vv[t]) * c);
        return;
    }
    int sb = blockIdx.x;
    int lane = tid & 31, wid = tid >> 5;
    int i0 = sb * 1024 + tid * 4;
    int v0 = 0, v1 = 0, v2 = 0, v3 = 0;
    if (i0 + 3 < N_F) {
        int4 q4 = *reinterpret_cast<const int4*>(&g_deg_dd[i0]);
        v0 = q4.x; v1 = q4.y; v2 = q4.z; v3 = q4.w;
    } else {
        if (i0 < N_F) v0 = g_deg_dd[i0];
        if (i0 + 1 < N_F) v1 = g_deg_dd[i0 + 1];
        if (i0 + 2 < N_F) v2 = g_deg_dd[i0 + 2];
        if (i0 + 3 < N_F) v3 = g_deg_dd[i0 + 3];
    }
    int s = v0 + v1 + v2 + v3;
    int inc = s;
#pragma unroll
    for (int o = 1; o < 32; o <<= 1) {
        int x = __shfl_up_sync(0xffffffffu, inc, o);
        if (lane >= o) inc += x;
    }
    __shared__ int wsum[8], wbase[8], sTotal, sBase;
    if (lane == 31) wsum[wid] = inc;
    __syncthreads();
    if (tid < 8) {
        int x = wsum[tid];
#pragma unroll
        for (int o = 1; o < 8; o <<= 1) {
            int y = __shfl_up_sync(0xffu, x, o);
            if (tid >= o) x += y;
        }
        wbase[tid] = x - wsum[tid];
        if (tid == 7) sTotal = x;
    }
    __syncthreads();
    int texcl = wbase[wid] + inc - s;
    int total = sTotal;
    if (wid == 0) {
        if (sb == 0) {
            if (lane == 0) {
                atomicExch(&g_lb[0], (2ull << 32) | (unsigned)total);
                sBase = 0;
            }
        } else {
            if (lane == 0) atomicExch(&g_lb[sb], (1ull << 32) | (unsigned)total);
            long long run = 0;
            int j = sb - 1;
            bool done = false;
            while (!done) {
                int jj = j - lane;
                unsigned long long tk = 0;
                if (jj >= 0) {
                    do { tk = atomicAdd(&g_lb[jj], 0ull); } while ((unsigned)(tk >> 32) == 0u);
                }
                unsigned incm = __ballot_sync(0xffffffffu, jj >= 0 && (unsigned)(tk >> 32) == 2u);
                int nvalid = min(32, j + 1);
                long long mv;
                if (incm) {
                    int fi = __ffs(incm) - 1;
                    mv = (jj >= 0 && lane <= fi) ? (long long)(unsigned)tk : 0;
                } else {
                    mv = (jj >= 0) ? (long long)(unsigned)tk : 0;
                }
#pragma unroll
                for (int o = 16; o; o >>= 1) mv += __shfl_down_sync(0xffffffffu, mv, o);
                run += __shfl_sync(0xffffffffu, mv, 0);
                if (incm) done = true;
                else {
                    j -= nvalid;
                    if (j < 0) done = true;
                }
            }
            if (lane == 0) {
                atomicExch(&g_lb[sb], (2ull << 32) | (unsigned)(run + total));
                sBase = (int)run;
            }
        }
    }
    __syncthreads();
    int e0 = sBase + texcl;
    if (i0 < N_F)     { g_cur[i0] = e0;         g_off[i0 + 1] = e0 + v0; }
    int e1 = e0 + v0;
    if (i0 + 1 < N_F) { g_cur[i0 + 1] = e1;     g_off[i0 + 2] = e1 + v1; }
    int e2 = e1 + v1;
    if (i0 + 2 < N_F) { g_cur[i0 + 2] = e2;     g_off[i0 + 3] = e2 + v2; }
    int e3 = e2 + v2;
    if (i0 + 3 < N_F) { g_cur[i0 + 3] = e3;     g_off[i0 + 4] = e3 + v3; }
    if (i0 == 0) g_off[0] = 0;
}

// ---------------- launch 2: CSR fill + hproc + att + weight pre-pack ----------------
__global__ void k_mid(const int* __restrict__ ds, const int* __restrict__ dd,
                      const float* __restrict__ Wenc, const float* __restrict__ benc,
                      const float* __restrict__ Wproc, const float* __restrict__ bproc,
                      const float* __restrict__ Wlin, const float* __restrict__ blin,
                      const float* __restrict__ Wa1, const float* __restrict__ ba1,
                      const float* __restrict__ Wo, const float* __restrict__ Wdec) {
    int tid = threadIdx.x;
    int bid = blockIdx.x;
    if (bid < FILLB) {
        int e = bid * 256 + tid;
        if (e >= NE) return;
        int pos = atomicAdd(&g_cur[dd[e]], 1);
        g_csr[pos] = ds[e];
        return;
    }
    if (bid == FILLB + HPB) {   // att precompute + vector copies
        int j = tid;
        if (j < AHD) {
            float u = 0.f, c = 0.f;
            for (int h = 0; h < HH; h++) {
                float ww = Wa1[h * AHD + j];
                u = fmaf(Wlin[h], ww, u);
                c = fmaf(blin[h], ww, c);
            }
            g_att[j] = u;
            g_att[AHD + j] = c + ba1[j];
            g_ba1[j] = ba1[j];
        }
        if (j < HH) g_Wo[j] = Wo[j];
        if (j == 0) {
            float k1 = 0.f, k2 = 0.f;
            for (int h = 0; h < HH; h++) { k1 = fmaf(Wlin[h], Wo[h], k1); k2 = fmaf(blin[h], Wo[h], k2); }
            g_att[2 * AHD] = k1;
            g_att[2 * AHD + 1] = k2;
        }
        return;
    }
    if (bid > FILLB + HPB) {    // weight pre-pack (28 blocks x 1024 words)
        int pb = bid - (FILLB + HPB + 1);
#pragma unroll
        for (int rep = 0; rep < 4; rep++) {
            int i = pb * 1024 + rep * 256 + tid;
            if (i < TT * 2048) {
                int t = i >> 11, r = i & 2047;
                int k2 = r >> 6, n = r & 63;
                g_wdp[i] = packh2(Wdec[t * 4096 + (2 * k2) * 64 + n],
                                  Wdec[t * 4096 + (2 * k2 + 1) * 64 + n]);
            } else {
                int j = i - TT * 2048;   // < 4096
                int k2 = j >> 7, n = j & 127;
                g_wap[j] = packh2(Wa1[(2 * k2) * 128 + n], Wa1[(2 * k2 + 1) * 128 + n]);
            }
        }
        return;
    }
    // ---- hproc ----
    __shared__ float sWe[TT * HH], sBe[TT * HH], sWp[TT * TT], sBp[TT];
    for (int i = tid; i < TT * HH; i += 256) { sWe[i] = Wenc[i]; sBe[i] = benc[i]; }
    if (tid < TT * TT) sWp[tid] = Wproc[tid];
    if (tid < TT) sBp[tid] = bproc[tid];
    __syncthreads();
    int n = (bid - FILLB) * 4 + (tid >> 6);
    int h = tid & 63;
    if (n >= N_H) return;
    float cde = rsqrtf(fmaxf((float)g_deg_de[n], 1.f));
    float csd = rsqrtf(fmaxf((float)g_deg_sd[n], 1.f));
    float he[TT];
#pragma unroll
    for (int t = 0; t < TT; t++) {
        float s = g_agg[n * TT + t] * cde;
        he[t] = lrelu(fmaf(s, sWe[t * HH + h], sBe[t * HH + h]));
    }
#pragma unroll
    for (int o = 0; o < TT; o++) {
        float v = sBp[o];
#pragma unroll
        for (int t = 0; t < TT; t++) v = fmaf(he[t], sWp[t * TT + o], v);
        v = fmaxf(v, 0.f) * csd;
        float vhi = __shfl_down_sync(0xffffffffu, v, 1);
        if ((h & 1) == 0)
            g_hp[((size_t)o * N_H + n) * 32 + (h >> 1)] = __floats2half2_rn(v, vhi);
    }
}

// ---------------- launch 3 (PROFILED): fused phase + recurrence ----------------
#define W_A     0
#define W_WD0   2304
#define W_WD1   4608
#define W_WA    6912
#define W_IDX   11264    // 448 words
#define W_PRM   11712    // 64 words (row permutation)
#define W_B0    11776
#define W_B1    11840
#define W_BA1   11904
#define W_WA2V  12032
#define W_WO    12160
#define W_SC    12224
#define W_S1O   12992
#define W_SUP   13760
#define W_SC2P  13888
#define W_W2P   14016
#define W_CDD   14144
#define W_TOT   14208
#define SMEM_PHASE (W_TOT * 4)

__global__ void __launch_bounds__(256)
k_phase(const float* __restrict__ bdec, const float* __restrict__ Wa2,
        const float* __restrict__ feat, const float* __restrict__ bo,
        float* __restrict__ out) {
    extern __shared__ unsigned usm[];
    unsigned* uA   = usm + W_A;
    unsigned* sIdx = usm + W_IDX;
    int*  sPrm  = (int*)(usm + W_PRM);
    float* fB0  = (float*)(usm + W_B0);
    float* fB1  = (float*)(usm + W_B1);
    float* fBa1 = (float*)(usm + W_BA1);
    float* fWa2 = (float*)(usm + W_WA2V);
    float* fWo  = (float*)(usm + W_WO);
    float* fSc  = (float*)(usm + W_SC);
    float* fS1o = (float*)(usm + W_S1O);
    float* fSuP = (float*)(usm + W_SUP);
    float* fSc2P= (float*)(usm + W_SC2P);
    float* fW2P = (float*)(usm + W_W2P);
    float* fCdd = (float*)(usm + W_CDD);

    int row0 = blockIdx.x * 64;
    int tid = threadIdx.x;
    int w = tid >> 5, lane = tid & 31;

    // once-per-block fills (vectorized copies of pre-packed weights)
    {
        const uint4* wav = reinterpret_cast<const uint4*>(g_wap);
#pragma unroll
        for (int rep = 0; rep < 4; rep++) {
            int i = rep * 256 + tid;          // 1024 uint4
            int k2 = i >> 5, n4 = (i & 31) * 4;
            *reinterpret_cast<uint4*>(&usm[W_WA + k2 * 136 + n4]) = wav[i];
        }
        const uint4* wdv = reinterpret_cast<const uint4*>(g_wdp);
#pragma unroll
        for (int rep = 0; rep < 2; rep++) {
            int i = rep * 256 + tid;          // 512 uint4 (t=0)
            int k2 = i >> 4, n4 = (i & 15) * 4;
            *reinterpret_cast<uint4*>(&usm[W_WD0 + k2 * 72 + n4]) = wdv[i];
        }
    }
    if (tid < 64) {
        fB0[tid] = bdec[tid];
        fWo[tid] = g_Wo[tid];
        int f = row0 + tid;
        fCdd[tid] = (f < N_F) ? rsqrtf(fmaxf((float)g_deg_dd[f], 1.f)) : 0.f;
    }
    if (tid < 128) {
        int p = (tid >> 5) + ((tid & 31) << 2);
        fSuP[p]  = g_att[tid];
        fSc2P[p] = g_att[128 + tid];
        fW2P[p]  = Wa2[tid];
        fBa1[tid] = g_ba1[tid];
        fWa2[tid] = Wa2[tid];
    }
    for (int i = tid; i < 1536; i += 256) fSc[i] = 0.f;   // fSc + fS1o

    // ---- degree-balanced row permutation (rank sort, descending) ----
    int E0 = g_off[row0];
    int rend = row0 + 64; if (rend > N_F) rend = N_F;
    int ecount = g_off[rend] - E0;
    if (tid < 64) {
        int f = row0 + tid;
        int l = (f < N_F) ? (g_off[f + 1] - g_off[f]) : 0;
        sIdx[tid] = (unsigned)l;     // temp: lengths
    }
    __syncthreads();
    if (tid < 64) {
        int li = (int)sIdx[tid];
        int rank = 0;
#pragma unroll 8
        for (int j = 0; j < 64; j++) {
            int lj = (int)sIdx[j];
            rank += (lj > li) || (lj == li && j < tid);
        }
        sPrm[rank] = tid;            // rank 0 = heaviest row
    }
    __syncthreads();

    // stage CSR as BYTE offsets (overwrites temp lengths)
    bool staged = (ecount <= IDXCAP);
    if (staged)
        for (int i = tid; i < ecount; i += 256)
            sIdx[i] = ((unsigned)g_csr[E0 + i]) << 7;

    // per-warp metadata for its 8 permuted rows
    int bofs[8], len[8];
#pragma unroll
    for (int rr = 0; rr < 8; rr++) {
        int pr = sPrm[w * 8 + rr];
        int f = row0 + pr;
        if (f < N_F) {
            int bg = g_off[f];
            bofs[rr] = bg - E0;
            len[rr] = g_off[f + 1] - bg;
        } else { bofs[rr] = 0; len[rr] = 0; }
    }
    int maxlen = 0;
#pragma unroll
    for (int rr = 0; rr < 8; rr++) maxlen = max(maxlen, len[rr]);

    int g = lane >> 2, q = lane & 3;
    int r0 = (w & 3) * 16;
    int colsel = w >> 2;

#pragma unroll 1
    for (int t = 0; t < TT; t++) {
        unsigned* uWdC = usm + ((t & 1) ? W_WD1 : W_WD0);
        unsigned* uWdN = usm + ((t & 1) ? W_WD0 : W_WD1);
        float* fBC = (t & 1) ? fB1 : fB0;
        float* fBN = (t & 1) ? fB0 : fB1;

        __syncthreads();
        // ---- gather: half2 accumulate, balanced 8-row joint walk ----
        const char* hbl = (const char*)g_hp + (size_t)t * (N_H * 128) + lane * 4;
        __half2 acc[8];
#pragma unroll
        for (int rr = 0; rr < 8; rr++) acc[rr] = __floats2half2_rn(0.f, 0.f);
        if (staged) {
            for (int s = 0; s < maxlen; s++) {
#pragma unroll
                for (int rr = 0; rr < 8; rr++) {
                    if (s < len[rr]) {
                        unsigned off = sIdx[bofs[rr] + s];
                        acc[rr] = __hadd2(acc[rr], *(const __half2*)(hbl + off));
                    }
                }
            }
        } else {
            for (int s = 0; s < maxlen; s++) {
#pragma unroll
                for (int rr = 0; rr < 8; rr++) {
                    if (s < len[rr]) {
                        unsigned off = ((unsigned)g_csr[E0 + bofs[rr] + s]) << 7;
                        acc[rr] = __hadd2(acc[rr], *(const __half2*)(hbl + off));
                    }
                }
            }
        }
#pragma unroll
        for (int rr = 0; rr < 8; rr++) {
            int pr = sPrm[w * 8 + rr];
            float cd = fCdd[pr];
            float2 v = __half22float2(acc[rr]);
            uA[pr * 36 + lane] = packh2(v.x * cd, v.y * cd);
        }
        __syncthreads();

        // ---- GEMM1 (fp16): space1 = leaky(A @ Wdec_t + b) ----
        float c1[4][4];
#pragma unroll
        for (int tn = 0; tn < 4; tn++)
#pragma unroll
            for (int i = 0; i < 4; i++) c1[tn][i] = 0.f;
#pragma unroll
        for (int ks = 0; ks < 4; ks++) {
            int kp = ks * 8;
            unsigned va0 = uA[(r0 + g) * 36 + kp + q];
            unsigned va1 = uA[(r0 + g + 8) * 36 + kp + q];
            unsigned va2 = uA[(r0 + g) * 36 + kp + q + 4];
            unsigned va3 = uA[(r0 + g + 8) * 36 + kp + q + 4];
#pragma unroll
            for (int tn = 0; tn < 4; tn++) {
                int nb = colsel * 32 + tn * 8 + g;
                unsigned b0 = uWdC[(kp + q) * 72 + nb];
                unsigned b1 = uWdC[(kp + q + 4) * 72 + nb];
                mma_f16(c1[tn][0], c1[tn][1], c1[tn][2], c1[tn][3], va0, va1, va2, va3, b0, b1);
            }
        }
        __syncthreads();
        // epilogue: bias+leaky -> hA; fused s1o partials from fragments
        __half2* hA = reinterpret_cast<__half2*>(uA);
        float p0 = 0.f, p1 = 0.f;
#pragma unroll
        for (int tn = 0; tn < 4; tn++) {
            int colp = colsel * 16 + tn * 4 + q;
            int col0 = 2 * colp;
            float v00 = lrelu(c1[tn][0] + fBC[col0]);
            float v01 = lrelu(c1[tn][1] + fBC[col0 + 1]);
            float v10 = lrelu(c1[tn][2] + fBC[col0]);
            float v11 = lrelu(c1[tn][3] + fBC[col0 + 1]);
            hA[(r0 + g) * 36 + colp]     = __floats2half2_rn(v00, v01);
            hA[(r0 + g + 8) * 36 + colp] = __floats2half2_rn(v10, v11);
            float w0 = fWo[col0], w1 = fWo[col0 + 1];
            p0 = fmaf(v00, w0, fmaf(v01, w1, p0));
            p1 = fmaf(v10, w0, fmaf(v11, w1, p1));
        }
        p0 += __shfl_down_sync(0xffffffffu, p0, 2, 4);
        p0 += __shfl_down_sync(0xffffffffu, p0, 1, 4);
        p1 += __shfl_down_sync(0xffffffffu, p1, 2, 4);
        p1 += __shfl_down_sync(0xffffffffu, p1, 1, 4);
        if (q == 0) {
            atomicAdd(&fS1o[t * 64 + r0 + g], p0);
            atomicAdd(&fS1o[t * 64 + r0 + g + 8], p1);
        }
        // prefetch next t's packed Wdec + bdec
        if (t + 1 < TT) {
            const uint4* wdv = reinterpret_cast<const uint4*>(g_wdp + (t + 1) * 2048);
#pragma unroll
            for (int rep = 0; rep < 2; rep++) {
                int i = rep * 256 + tid;
                int k2 = i >> 4, n4 = (i & 15) * 4;
                *reinterpret_cast<uint4*>(&uWdN[k2 * 72 + n4]) = wdv[i];
            }
            if (tid < 64) fBN[tid] = bdec[(t + 1) * 64 + tid];
        }
        __syncthreads();

        // ---- GEMM2: z = space1 @ Wa1; score1 = tanh(z+ba1)@Wa2 ----
        float sc0 = 0.f, sc1 = 0.f;
#pragma unroll
        for (int pass = 0; pass < 2; ++pass) {
            float z[4][4];
#pragma unroll
            for (int tn = 0; tn < 4; tn++)
#pragma unroll
                for (int i = 0; i < 4; i++) z[tn][i] = 0.f;
#pragma unroll
            for (int ks = 0; ks < 4; ks++) {
                int kp = ks * 8;
                unsigned va0 = uA[(r0 + g) * 36 + kp + q];
                unsigned va1 = uA[(r0 + g + 8) * 36 + kp + q];
                unsigned va2 = uA[(r0 + g) * 36 + kp + q + 4];
                unsigned va3 = uA[(r0 + g + 8) * 36 + kp + q + 4];
#pragma unroll
                for (int tn = 0; tn < 4; tn++) {
                    int cb = colsel * 64 + pass * 32 + tn * 8 + g;
                    unsigned b0 = usm[W_WA + (kp + q) * 136 + cb];
                    unsigned b1 = usm[W_WA + (kp + q + 4) * 136 + cb];
                    mma_f16(z[tn][0], z[tn][1], z[tn][2], z[tn][3], va0, va1, va2, va3, b0, b1);
                }
            }
#pragma unroll
            for (int tn = 0; tn < 4; tn++) {
                int col0 = colsel * 64 + pass * 32 + tn * 8 + 2 * q;
                sc0 = fmaf(fast_tanh(z[tn][0] + fBa1[col0]),     fWa2[col0],     sc0);
                sc0 = fmaf(fast_tanh(z[tn][1] + fBa1[col0 + 1]), fWa2[col0 + 1], sc0);
                sc1 = fmaf(fast_tanh(z[tn][2] + fBa1[col0]),     fWa2[col0],     sc1);
                sc1 = fmaf(fast_tanh(z[tn][3] + fBa1[col0 + 1]), fWa2[col0 + 1], sc1);
            }
        }
        sc0 += __shfl_down_sync(0xffffffffu, sc0, 2, 4);
        sc0 += __shfl_down_sync(0xffffffffu, sc0, 1, 4);
        sc1 += __shfl_down_sync(0xffffffffu, sc1, 2, 4);
        sc1 += __shfl_down_sync(0xffffffffu, sc1, 1, 4);
        if (q == 0) {
            atomicAdd(&fSc[t * 64 + r0 + g], sc0);
            atomicAdd(&fSc[t * 64 + r0 + g + 8], sc1);
        }
    }
    __syncthreads();

    // ---- fused recurrence: 4 threads per row ----
    int rowi = tid >> 2, sub = tid & 3;
    int f = row0 + rowi;
    float y = 0.f;
    if (f < N_F) y = nan0(feat[(size_t)f * 12 + 11]);
    float k1 = g_att[256], k2v = g_att[257], b0v = bo[0];
#pragma unroll 1
    for (int t = 0; t < TT; t++) {
        float p = 0.f;
#pragma unroll 8
        for (int jj = 0; jj < 32; jj++) {
            int pi = sub + 4 * jj;
            p = fmaf(fast_tanh(fmaf(y, fSuP[pi], fSc2P[pi])), fW2P[pi], p);
        }
        p += __shfl_xor_sync(0xffffffffu, p, 1, 4);
        p += __shfl_xor_sync(0xffffffffu, p, 2, 4);
        float s2 = p;
        float s1 = fSc[t * 64 + rowi];
        float mx = fmaxf(s1, s2);
        float e1 = __expf(s1 - mx), e2 = __expf(s2 - mx);
        float al = e1 / (e1 + e2);
        y = fmaf(al, fS1o[t * 64 + rowi], (1.f - al) * fmaf(y, k1, k2v)) + b0v;
        if (f < N_F && sub == 0) out[(size_t)t * N_F + f] = y;
    }
}

extern "C" void kernel_launch(void* const* d_in, const int* in_sizes, int n_in,
                              void* d_out, int out_size) {
    const float* feat  = (const float*)d_in[0];
    const int*   es    = (const int*)d_in[1];
    const int*   ed    = (const int*)d_in[2];
    const int*   ds    = (const int*)d_in[3];
    const int*   dd    = (const int*)d_in[4];
    const float* Wenc  = (const float*)d_in[5];
    const float* benc  = (const float*)d_in[6];
    const float* Wproc = (const float*)d_in[7];
    const float* bproc = (const float*)d_in[8];
    const float* Wdec  = (const float*)d_in[9];
    const float* bdec  = (const float*)d_in[10];
    const float* Wlin  = (const float*)d_in[11];
    const float* blin  = (const float*)d_in[12];
    const float* Wa1   = (const float*)d_in[13];
    const float* ba1   = (const float*)d_in[14];
    const float* Wa2   = (const float*)d_in[15];
    const float* Wo    = (const float*)d_in[17];
    const float* bo    = (const float*)d_in[18];
    float* out = (float*)d_out;

    cudaFuncSetAttribute(k_phase, cudaFuncAttributeMaxDynamicSharedMemorySize, SMEM_PHASE);

    void *p_se, *p_de, *p_sd, *p_dd, *p_agg, *p_lb;
    cudaGetSymbolAddress(&p_se, g_deg_se);
    cudaGetSymbolAddress(&p_de, g_deg_de);
    cudaGetSymbolAddress(&p_sd, g_deg_sd);
    cudaGetSymbolAddress(&p_dd, g_deg_dd);
    cudaGetSymbolAddress(&p_agg, g_agg);
    cudaGetSymbolAddress(&p_lb, g_lb);
    cudaMemsetAsync(p_se, 0, N_F * sizeof(int));
    cudaMemsetAsync(p_de, 0, N_H * sizeof(int));
    cudaMemsetAsync(p_sd, 0, N_H * sizeof(int));
    cudaMemsetAsync(p_dd, 0, N_F * sizeof(int));
    cudaMemsetAsync(p_agg, 0, N_H * TT * sizeof(float));
    cudaMemsetAsync(p_lb, 0, SCANB * sizeof(unsigned long long));

    k_deg<<<(NE + 255) / 256, 256>>>(es, ed, ds, dd);
    k_enc_scan<<<SCANB + ENCB, 256>>>(feat, es, ed);
    k_mid<<<FILLB + HPB + 1 + PACKB, 256>>>(ds, dd, Wenc, benc, Wproc, bproc,
                                            Wlin, blin, Wa1, ba1, Wo, Wdec);
    k_phase<<<(N_F + 63) / 64, 256, SMEM_PHASE>>>(bdec, Wa2, feat, bo, out);
}

// round 14
// speedup vs baseline: 1.0529x; 1.0529x over previous
#include <cuda_runtime.h>
#include <cuda_fp16.h>
#include <math.h>
#include <stdint.h>

#define N_F 100000
#define N_H 49152
#define NE  400000
#define TT  12
#define HH  64
#define AHD 128
#define SCANB 98
#define ENCB  ((NE + 255) / 256)
#define FILLB ((NE + 255) / 256)
#define HPB   (N_H / 16)             // 3072 blocks, 16 nodes each
#define PACKB 28                     // 28*1024 = 24576 (Wdec) + 4096 (Wa1)
#define IDXCAP 512

__device__ int     g_deg_se[N_F];
__device__ int     g_deg_de[N_H];
__device__ int     g_deg_sd[N_H];
__device__ int     g_deg_dd[N_F];
__device__ float   g_agg[N_H * TT];
__device__ __half2 g_hp[(size_t)TT * N_H * 32];   // (t, n, h/2)
__device__ int     g_off[N_F + 1];
__device__ int     g_cur[N_F];
__device__ int     g_csr[NE];
__device__ unsigned long long g_lb[SCANB];
__device__ float   g_att[2 * AHD + 2];            // u[128], c2[128], k1, k2
__device__ float   g_ba1[AHD];
__device__ float   g_Wo[HH];
__device__ __align__(16) unsigned g_wdp[TT * 2048];  // packed Wdec fp16 pairs
__device__ __align__(16) unsigned g_wap[4096];       // packed Wa1 fp16 pairs

__device__ __forceinline__ float fast_tanh(float x) {
    float y;
    asm("tanh.approx.f32 %0, %1;" : "=f"(y) : "f"(x));
    return y;
}
__device__ __forceinline__ float nan0(float x) {
    x = (x == x) ? x : 0.f;
    return fminf(fmaxf(x, -3.402823466e38f), 3.402823466e38f);
}
__device__ __forceinline__ float lrelu(float x) { return x > 0.f ? x : 0.01f * x; }
__device__ __forceinline__ unsigned packh2(float a, float b) {
    __half2 h = __floats2half2_rn(a, b);
    return *reinterpret_cast<unsigned*>(&h);
}
__device__ __forceinline__ void mma_f16(float& c0, float& c1, float& c2, float& c3,
                                        unsigned a0, unsigned a1, unsigned a2, unsigned a3,
                                        unsigned b0, unsigned b1) {
    asm("mma.sync.aligned.m16n8k16.row.col.f32.f16.f16.f32 "
        "{%0,%1,%2,%3},{%4,%5,%6,%7},{%8,%9},{%0,%1,%2,%3};"
        : "+f"(c0), "+f"(c1), "+f"(c2), "+f"(c3)
        : "r"(a0), "r"(a1), "r"(a2), "r"(a3), "r"(b0), "r"(b1));
}

// ---------------- launch 0: degrees ----------------
__global__ void k_deg(const int* __restrict__ es, const int* __restrict__ ed,
                      const int* __restrict__ ds, const int* __restrict__ dd) {
    int e = blockIdx.x * blockDim.x + threadIdx.x;
    if (e >= NE) return;
    atomicAdd(&g_deg_se[es[e]], 1);
    atomicAdd(&g_deg_de[ed[e]], 1);
    atomicAdd(&g_deg_sd[ds[e]], 1);
    atomicAdd(&g_deg_dd[dd[e]], 1);
}

// ---------------- launch 1: decoupled-lookback scan + encoder scatter ----------------
__global__ void k_enc_scan(const float* __restrict__ feat, const int* __restrict__ es,
                           const int* __restrict__ ed) {
    int tid = threadIdx.x;
    if (blockIdx.x >= SCANB) {
        int e = (blockIdx.x - SCANB) * 256 + tid;
        if (e >= NE) return;
        int s = es[e], d = ed[e];
        float c = rsqrtf(fmaxf((float)g_deg_se[s], 1.f));
        const float4* fp = reinterpret_cast<const float4*>(feat + (size_t)s * 12);
        float4 v0 = fp[0], v1 = fp[1], v2 = fp[2];
        float vv[12] = {v0.x, v0.y, v0.z, v0.w, v1.x, v1.y, v1.z, v1.w, v2.x, v2.y, v2.z, v2.w};
        float* ap = g_agg + (size_t)d * TT;
#pragma unroll
        for (int t = 0; t < 12; t++) atomicAdd(ap + t, nan0(vv[t]) * c);
        return;
    }
    int sb = blockIdx.x;
    int lane = tid & 31, wid = tid >> 5;
    int i0 = sb * 1024 + tid * 4;
    int v0 = 0, v1 = 0, v2 = 0, v3 = 0;
    if (i0 + 3 < N_F) {
        int4 q4 = *reinterpret_cast<const int4*>(&g_deg_dd[i0]);
        v0 = q4.x; v1 = q4.y; v2 = q4.z; v3 = q4.w;
    } else {
        if (i0 < N_F) v0 = g_deg_dd[i0];
        if (i0 + 1 < N_F) v1 = g_deg_dd[i0 + 1];
        if (i0 + 2 < N_F) v2 = g_deg_dd[i0 + 2];
        if (i0 + 3 < N_F) v3 = g_deg_dd[i0 + 3];
    }
    int s = v0 + v1 + v2 + v3;
    int inc = s;
#pragma unroll
    for (int o = 1; o < 32; o <<= 1) {
        int x = __shfl_up_sync(0xffffffffu, inc, o);
        if (lane >= o) inc += x;
    }
    __shared__ int wsum[8], wbase[8], sTotal, sBase;
    if (lane == 31) wsum[wid] = inc;
    __syncthreads();
    if (tid < 8) {
        int x = wsum[tid];
#pragma unroll
        for (int o = 1; o < 8; o <<= 1) {
            int y = __shfl_up_sync(0xffu, x, o);
            if (tid >= o) x += y;
        }
        wbase[tid] = x - wsum[tid];
        if (tid == 7) sTotal = x;
    }
    __syncthreads();
    int texcl = wbase[wid] + inc - s;
    int total = sTotal;
    if (wid == 0) {
        if (sb == 0) {
            if (lane == 0) {
                atomicExch(&g_lb[0], (2ull << 32) | (unsigned)total);
                sBase = 0;
            }
        } else {
            if (lane == 0) atomicExch(&g_lb[sb], (1ull << 32) | (unsigned)total);
            long long run = 0;
            int j = sb - 1;
            bool done = false;
            while (!done) {
                int jj = j - lane;
                unsigned long long tk = 0;
                if (jj >= 0) {
                    do { tk = atomicAdd(&g_lb[jj], 0ull); } while ((unsigned)(tk >> 32) == 0u);
                }
                unsigned incm = __ballot_sync(0xffffffffu, jj >= 0 && (unsigned)(tk >> 32) == 2u);
                int nvalid = min(32, j + 1);
                long long mv;
                if (incm) {
                    int fi = __ffs(incm) - 1;
                    mv = (jj >= 0 && lane <= fi) ? (long long)(unsigned)tk : 0;
                } else {
                    mv = (jj >= 0) ? (long long)(unsigned)tk : 0;
                }
#pragma unroll
                for (int o = 16; o; o >>= 1) mv += __shfl_down_sync(0xffffffffu, mv, o);
                run += __shfl_sync(0xffffffffu, mv, 0);
                if (incm) done = true;
                else {
                    j -= nvalid;
                    if (j < 0) done = true;
                }
            }
            if (lane == 0) {
                atomicExch(&g_lb[sb], (2ull << 32) | (unsigned)(run + total));
                sBase = (int)run;
            }
        }
    }
    __syncthreads();
    int e0 = sBase + texcl;
    if (i0 < N_F)     { g_cur[i0] = e0;         g_off[i0 + 1] = e0 + v0; }
    int e1 = e0 + v0;
    if (i0 + 1 < N_F) { g_cur[i0 + 1] = e1;     g_off[i0 + 2] = e1 + v1; }
    int e2 = e1 + v1;
    if (i0 + 2 < N_F) { g_cur[i0 + 2] = e2;     g_off[i0 + 3] = e2 + v2; }
    int e3 = e2 + v2;
    if (i0 + 3 < N_F) { g_cur[i0 + 3] = e3;     g_off[i0 + 4] = e3 + v3; }
    if (i0 == 0) g_off[0] = 0;
}

// ---------------- launch 2: CSR fill + hproc(16 nodes/blk) + att + weight pre-pack ----------------
__global__ void k_mid(const int* __restrict__ ds, const int* __restrict__ dd,
                      const float* __restrict__ Wenc, const float* __restrict__ benc,
                      const float* __restrict__ Wproc, const float* __restrict__ bproc,
                      const float* __restrict__ Wlin, const float* __restrict__ blin,
                      const float* __restrict__ Wa1, const float* __restrict__ ba1,
                      const float* __restrict__ Wo, const float* __restrict__ Wdec) {
    int tid = threadIdx.x;
    int bid = blockIdx.x;
    if (bid < FILLB) {
        int e = bid * 256 + tid;
        if (e >= NE) return;
        int pos = atomicAdd(&g_cur[dd[e]], 1);
        g_csr[pos] = ds[e];
        return;
    }
    if (bid == FILLB + HPB) {   // att precompute + vector copies
        int j = tid;
        if (j < AHD) {
            float u = 0.f, c = 0.f;
            for (int h = 0; h < HH; h++) {
                float ww = Wa1[h * AHD + j];
                u = fmaf(Wlin[h], ww, u);
                c = fmaf(blin[h], ww, c);
            }
            g_att[j] = u;
            g_att[AHD + j] = c + ba1[j];
            g_ba1[j] = ba1[j];
        }
        if (j < HH) g_Wo[j] = Wo[j];
        if (j == 0) {
            float k1 = 0.f, k2 = 0.f;
            for (int h = 0; h < HH; h++) { k1 = fmaf(Wlin[h], Wo[h], k1); k2 = fmaf(blin[h], Wo[h], k2); }
            g_att[2 * AHD] = k1;
            g_att[2 * AHD + 1] = k2;
        }
        return;
    }
    if (bid > FILLB + HPB) {    // weight pre-pack (28 blocks x 1024 words)
        int pb = bid - (FILLB + HPB + 1);
#pragma unroll
        for (int rep = 0; rep < 4; rep++) {
            int i = pb * 1024 + rep * 256 + tid;
            if (i < TT * 2048) {
                int t = i >> 11, r = i & 2047;
                int k2 = r >> 6, n = r & 63;
                g_wdp[i] = packh2(Wdec[t * 4096 + (2 * k2) * 64 + n],
                                  Wdec[t * 4096 + (2 * k2 + 1) * 64 + n]);
            } else {
                int j = i - TT * 2048;   // < 4096
                int k2 = j >> 7, n = j & 127;
                g_wap[j] = packh2(Wa1[(2 * k2) * 128 + n], Wa1[(2 * k2 + 1) * 128 + n]);
            }
        }
        return;
    }
    // ---- hproc: 16 nodes per block ----
    __shared__ float sWe[TT * HH], sBe[TT * HH], sWp[TT * TT], sBp[TT];
    for (int i = tid; i < TT * HH; i += 256) { sWe[i] = Wenc[i]; sBe[i] = benc[i]; }
    if (tid < TT * TT) sWp[tid] = Wproc[tid];
    if (tid < TT) sBp[tid] = bproc[tid];
    __syncthreads();
    int nb0 = (bid - FILLB) * 16;
    int h = tid & 63;
#pragma unroll 1
    for (int nn = 0; nn < 4; nn++) {
        int n = nb0 + nn * 4 + (tid >> 6);
        float cde = rsqrtf(fmaxf((float)g_deg_de[n], 1.f));
        float csd = rsqrtf(fmaxf((float)g_deg_sd[n], 1.f));
        const float4* ap = reinterpret_cast<const float4*>(g_agg + n * TT);
        float4 a0 = ap[0], a1 = ap[1], a2 = ap[2];
        float av[12] = {a0.x, a0.y, a0.z, a0.w, a1.x, a1.y, a1.z, a1.w, a2.x, a2.y, a2.z, a2.w};
        float he[TT];
#pragma unroll
        for (int t = 0; t < TT; t++)
            he[t] = lrelu(fmaf(av[t] * cde, sWe[t * HH + h], sBe[t * HH + h]));
#pragma unroll
        for (int o = 0; o < TT; o++) {
            float v = sBp[o];
#pragma unroll
            for (int t = 0; t < TT; t++) v = fmaf(he[t], sWp[t * TT + o], v);
            v = fmaxf(v, 0.f) * csd;
            float vhi = __shfl_down_sync(0xffffffffu, v, 1);
            if ((h & 1) == 0)
                g_hp[((size_t)o * N_H + n) * 32 + (h >> 1)] = __floats2half2_rn(v, vhi);
        }
    }
}

// ---------------- launch 3 (PROFILED): fused phase + recurrence (R8-exact) ----------------
#define W_A     0
#define W_WD0   2304
#define W_WD1   4608
#define W_WA    6912
#define W_IDX   11264
#define W_B0    11776
#define W_B1    11840
#define W_BA1   11904
#define W_WA2V  12032
#define W_WO    12160
#define W_SC    12224
#define W_S1O   12992
#define W_SUP   13760
#define W_SC2P  13888
#define W_W2P   14016
#define W_CDD   14144
#define W_TOT   14208
#define SMEM_PHASE (W_TOT * 4)

__global__ void __launch_bounds__(256)
k_phase(const float* __restrict__ bdec, const float* __restrict__ Wa2,
        const float* __restrict__ feat, const float* __restrict__ bo,
        float* __restrict__ out) {
    extern __shared__ unsigned usm[];
    unsigned* uA   = usm + W_A;
    unsigned* sIdx = usm + W_IDX;
    float* fB0  = (float*)(usm + W_B0);
    float* fB1  = (float*)(usm + W_B1);
    float* fBa1 = (float*)(usm + W_BA1);
    float* fWa2 = (float*)(usm + W_WA2V);
    float* fWo  = (float*)(usm + W_WO);
    float* fSc  = (float*)(usm + W_SC);
    float* fS1o = (float*)(usm + W_S1O);
    float* fSuP = (float*)(usm + W_SUP);
    float* fSc2P= (float*)(usm + W_SC2P);
    float* fW2P = (float*)(usm + W_W2P);
    float* fCdd = (float*)(usm + W_CDD);

    int row0 = blockIdx.x * 64;
    int tid = threadIdx.x;
    int w = tid >> 5, lane = tid & 31;

    // once-per-block fills (vectorized copies of pre-packed weights)
    {
        const uint4* wav = reinterpret_cast<const uint4*>(g_wap);
#pragma unroll
        for (int rep = 0; rep < 4; rep++) {
            int i = rep * 256 + tid;          // 1024 uint4
            int k2 = i >> 5, n4 = (i & 31) * 4;
            *reinterpret_cast<uint4*>(&usm[W_WA + k2 * 136 + n4]) = wav[i];
        }
        const uint4* wdv = reinterpret_cast<const uint4*>(g_wdp);
#pragma unroll
        for (int rep = 0; rep < 2; rep++) {
            int i = rep * 256 + tid;          // 512 uint4 (t=0)
            int k2 = i >> 4, n4 = (i & 15) * 4;
            *reinterpret_cast<uint4*>(&usm[W_WD0 + k2 * 72 + n4]) = wdv[i];
        }
    }
    if (tid < 64) {
        fB0[tid] = bdec[tid];
        fWo[tid] = g_Wo[tid];
        int f = row0 + tid;
        fCdd[tid] = (f < N_F) ? rsqrtf(fmaxf((float)g_deg_dd[f], 1.f)) : 0.f;
    }
    if (tid < 128) {
        int p = (tid >> 5) + ((tid & 31) << 2);
        fSuP[p]  = g_att[tid];
        fSc2P[p] = g_att[128 + tid];
        fW2P[p]  = Wa2[tid];
        fBa1[tid] = g_ba1[tid];
        fWa2[tid] = Wa2[tid];
    }
    for (int i = tid; i < 1536; i += 256) fSc[i] = 0.f;   // fSc + fS1o

    // tile edge range; stage CSR as BYTE offsets
    int E0 = g_off[row0];
    int rend = row0 + 64; if (rend > N_F) rend = N_F;
    int ecount = g_off[rend] - E0;
    bool staged = (ecount <= IDXCAP);
    if (staged)
        for (int i = tid; i < ecount; i += 256)
            sIdx[i] = ((unsigned)g_csr[E0 + i]) << 7;

    int bofs[8], len[8];
#pragma unroll
    for (int rr = 0; rr < 8; rr++) {
        int f = row0 + w * 8 + rr;
        if (f < N_F) {
            int bg = g_off[f];
            bofs[rr] = bg - E0;
            len[rr] = g_off[f + 1] - bg;
        } else { bofs[rr] = 0; len[rr] = 0; }
    }
    int maxlen = 0;
#pragma unroll
    for (int rr = 0; rr < 8; rr++) maxlen = max(maxlen, len[rr]);

    int g = lane >> 2, q = lane & 3;
    int r0 = (w & 3) * 16;
    int colsel = w >> 2;

#pragma unroll 1
    for (int t = 0; t < TT; t++) {
        unsigned* uWdC = usm + ((t & 1) ? W_WD1 : W_WD0);
        unsigned* uWdN = usm + ((t & 1) ? W_WD0 : W_WD1);
        float* fBC = (t & 1) ? fB1 : fB0;
        float* fBN = (t & 1) ? fB0 : fB1;

        __syncthreads();
        // ---- gather: half2 accumulate, 32-bit offsets, joint 8-row walk ----
        const char* hbl = (const char*)g_hp + (size_t)t * (N_H * 128) + lane * 4;
        __half2 acc[8];
#pragma unroll
        for (int rr = 0; rr < 8; rr++) acc[rr] = __floats2half2_rn(0.f, 0.f);
        if (staged) {
            for (int s = 0; s < maxlen; s++) {
#pragma unroll
                for (int rr = 0; rr < 8; rr++) {
                    if (s < len[rr]) {
                        unsigned off = sIdx[bofs[rr] + s];
                        acc[rr] = __hadd2(acc[rr], *(const __half2*)(hbl + off));
                    }
                }
            }
        } else {
            for (int s = 0; s < maxlen; s++) {
#pragma unroll
                for (int rr = 0; rr < 8; rr++) {
                    if (s < len[rr]) {
                        unsigned off = ((unsigned)g_csr[E0 + bofs[rr] + s]) << 7;
                        acc[rr] = __hadd2(acc[rr], *(const __half2*)(hbl + off));
                    }
                }
            }
        }
#pragma unroll
        for (int rr = 0; rr < 8; rr++) {
            int r = w * 8 + rr;
            float cd = fCdd[r];
            float2 v = __half22float2(acc[rr]);
            uA[r * 36 + lane] = packh2(v.x * cd, v.y * cd);
        }
        __syncthreads();

        // ---- GEMM1 (fp16): space1 = leaky(A @ Wdec_t + b) ----
        float c1[4][4];
#pragma unroll
        for (int tn = 0; tn < 4; tn++)
#pragma unroll
            for (int i = 0; i < 4; i++) c1[tn][i] = 0.f;
#pragma unroll
        for (int ks = 0; ks < 4; ks++) {
            int kp = ks * 8;
            unsigned va0 = uA[(r0 + g) * 36 + kp + q];
            unsigned va1 = uA[(r0 + g + 8) * 36 + kp + q];
            unsigned va2 = uA[(r0 + g) * 36 + kp + q + 4];
            unsigned va3 = uA[(r0 + g + 8) * 36 + kp + q + 4];
#pragma unroll
            for (int tn = 0; tn < 4; tn++) {
                int nb = colsel * 32 + tn * 8 + g;
                unsigned b0 = uWdC[(kp + q) * 72 + nb];
                unsigned b1 = uWdC[(kp + q + 4) * 72 + nb];
                mma_f16(c1[tn][0], c1[tn][1], c1[tn][2], c1[tn][3], va0, va1, va2, va3, b0, b1);
            }
        }
        __syncthreads();
        // epilogue: bias+leaky -> hA; fused s1o partials from fragments
        __half2* hA = reinterpret_cast<__half2*>(uA);
        float p0 = 0.f, p1 = 0.f;
#pragma unroll
        for (int tn = 0; tn < 4; tn++) {
            int colp = colsel * 16 + tn * 4 + q;
            int col0 = 2 * colp;
            float v00 = lrelu(c1[tn][0] + fBC[col0]);
            float v01 = lrelu(c1[tn][1] + fBC[col0 + 1]);
            float v10 = lrelu(c1[tn][2] + fBC[col0]);
            float v11 = lrelu(c1[tn][3] + fBC[col0 + 1]);
            hA[(r0 + g) * 36 + colp]     = __floats2half2_rn(v00, v01);
            hA[(r0 + g + 8) * 36 + colp] = __floats2half2_rn(v10, v11);
            float w0 = fWo[col0], w1 = fWo[col0 + 1];
            p0 = fmaf(v00, w0, fmaf(v01, w1, p0));
            p1 = fmaf(v10, w0, fmaf(v11, w1, p1));
        }
        p0 += __shfl_down_sync(0xffffffffu, p0, 2, 4);
        p0 += __shfl_down_sync(0xffffffffu, p0, 1, 4);
        p1 += __shfl_down_sync(0xffffffffu, p1, 2, 4);
        p1 += __shfl_down_sync(0xffffffffu, p1, 1, 4);
        if (q == 0) {
            atomicAdd(&fS1o[t * 64 + r0 + g], p0);
            atomicAdd(&fS1o[t * 64 + r0 + g + 8], p1);
        }
        // prefetch next t's packed Wdec + bdec
        if (t + 1 < TT) {
            const uint4* wdv = reinterpret_cast<const uint4*>(g_wdp + (t + 1) * 2048);
#pragma unroll
            for (int rep = 0; rep < 2; rep++) {
                int i = rep * 256 + tid;
                int k2 = i >> 4, n4 = (i & 15) * 4;
                *reinterpret_cast<uint4*>(&uWdN[k2 * 72 + n4]) = wdv[i];
            }
            if (tid < 64) fBN[tid] = bdec[(t + 1) * 64 + tid];
        }
        __syncthreads();

        // ---- GEMM2: z = space1 @ Wa1; score1 = tanh(z+ba1)@Wa2 ----
        float sc0 = 0.f, sc1 = 0.f;
#pragma unroll
        for (int pass = 0; pass < 2; ++pass) {
            float z[4][4];
#pragma unroll
            for (int tn = 0; tn < 4; tn++)
#pragma unroll
                for (int i = 0; i < 4; i++) z[tn][i] = 0.f;
#pragma unroll
            for (int ks = 0; ks < 4; ks++) {
                int kp = ks * 8;
                unsigned va0 = uA[(r0 + g) * 36 + kp + q];
                unsigned va1 = uA[(r0 + g + 8) * 36 + kp + q];
                unsigned va2 = uA[(r0 + g) * 36 + kp + q + 4];
                unsigned va3 = uA[(r0 + g + 8) * 36 + kp + q + 4];
#pragma unroll
                for (int tn = 0; tn < 4; tn++) {
                    int cb = colsel * 64 + pass * 32 + tn * 8 + g;
                    unsigned b0 = usm[W_WA + (kp + q) * 136 + cb];
                    unsigned b1 = usm[W_WA + (kp + q + 4) * 136 + cb];
                    mma_f16(z[tn][0], z[tn][1], z[tn][2], z[tn][3], va0, va1, va2, va3, b0, b1);
                }
            }
#pragma unroll
            for (int tn = 0; tn < 4; tn++) {
                int col0 = colsel * 64 + pass * 32 + tn * 8 + 2 * q;
                sc0 = fmaf(fast_tanh(z[tn][0] + fBa1[col0]),     fWa2[col0],     sc0);
                sc0 = fmaf(fast_tanh(z[tn][1] + fBa1[col0 + 1]), fWa2[col0 + 1], sc0);
                sc1 = fmaf(fast_tanh(z[tn][2] + fBa1[col0]),     fWa2[col0],     sc1);
                sc1 = fmaf(fast_tanh(z[tn][3] + fBa1[col0 + 1]), fWa2[col0 + 1], sc1);
            }
        }
        sc0 += __shfl_down_sync(0xffffffffu, sc0, 2, 4);
        sc0 += __shfl_down_sync(0xffffffffu, sc0, 1, 4);
        sc1 += __shfl_down_sync(0xffffffffu, sc1, 2, 4);
        sc1 += __shfl_down_sync(0xffffffffu, sc1, 1, 4);
        if (q == 0) {
            atomicAdd(&fSc[t * 64 + r0 + g], sc0);
            atomicAdd(&fSc[t * 64 + r0 + g + 8], sc1);
        }
    }
    __syncthreads();

    // ---- fused recurrence: 4 threads per row ----
    int rowi = tid >> 2, sub = tid & 3;
    int f = row0 + rowi;
    float y = 0.f;
    if (f < N_F) y = nan0(feat[(size_t)f * 12 + 11]);
    float k1 = g_att[256], k2v = g_att[257], b0v = bo[0];
#pragma unroll 1
    for (int t = 0; t < TT; t++) {
        float p = 0.f;
#pragma unroll 8
        for (int jj = 0; jj < 32; jj++) {
            int pi = sub + 4 * jj;
            p = fmaf(fast_tanh(fmaf(y, fSuP[pi], fSc2P[pi])), fW2P[pi], p);
        }
        p += __shfl_xor_sync(0xffffffffu, p, 1, 4);
        p += __shfl_xor_sync(0xffffffffu, p, 2, 4);
        float s2 = p;
        float s1 = fSc[t * 64 + rowi];
        float mx = fmaxf(s1, s2);
        float e1 = __expf(s1 - mx), e2 = __expf(s2 - mx);
        float al = e1 / (e1 + e2);
        y = fmaf(al, fS1o[t * 64 + rowi], (1.f - al) * fmaf(y, k1, k2v)) + b0v;
        if (f < N_F && sub == 0) out[(size_t)t * N_F + f] = y;
    }
}

extern "C" void kernel_launch(void* const* d_in, const int* in_sizes, int n_in,
                              void* d_out, int out_size) {
    const float* feat  = (const float*)d_in[0];
    const int*   es    = (const int*)d_in[1];
    const int*   ed    = (const int*)d_in[2];
    const int*   ds    = (const int*)d_in[3];
    const int*   dd    = (const int*)d_in[4];
    const float* Wenc  = (const float*)d_in[5];
    const float* benc  = (const float*)d_in[6];
    const float* Wproc = (const float*)d_in[7];
    const float* bproc = (const float*)d_in[8];
    const float* Wdec  = (const float*)d_in[9];
    const float* bdec  = (const float*)d_in[10];
    const float* Wlin  = (const float*)d_in[11];
    const float* blin  = (const float*)d_in[12];
    const float* Wa1   = (const float*)d_in[13];
    const float* ba1   = (const float*)d_in[14];
    const float* Wa2   = (const float*)d_in[15];
    const float* Wo    = (const float*)d_in[17];
    const float* bo    = (const float*)d_in[18];
    float* out = (float*)d_out;

    cudaFuncSetAttribute(k_phase, cudaFuncAttributeMaxDynamicSharedMemorySize, SMEM_PHASE);

    void *p_se, *p_de, *p_sd, *p_dd, *p_agg, *p_lb;
    cudaGetSymbolAddress(&p_se, g_deg_se);
    cudaGetSymbolAddress(&p_de, g_deg_de);
    cudaGetSymbolAddress(&p_sd, g_deg_sd);
    cudaGetSymbolAddress(&p_dd, g_deg_dd);
    cudaGetSymbolAddress(&p_agg, g_agg);
    cudaGetSymbolAddress(&p_lb, g_lb);
    cudaMemsetAsync(p_se, 0, N_F * sizeof(int));
    cudaMemsetAsync(p_de, 0, N_H * sizeof(int));
    cudaMemsetAsync(p_sd, 0, N_H * sizeof(int));
    cudaMemsetAsync(p_dd, 0, N_F * sizeof(int));
    cudaMemsetAsync(p_agg, 0, N_H * TT * sizeof(float));
    cudaMemsetAsync(p_lb, 0, SCANB * sizeof(unsigned long long));

    k_deg<<<(NE + 255) / 256, 256>>>(es, ed, ds, dd);
    k_enc_scan<<<SCANB + ENCB, 256>>>(feat, es, ed);
    k_mid<<<FILLB + HPB + 1 + PACKB, 256>>>(ds, dd, Wenc, benc, Wproc, bproc,
                                            Wlin, blin, Wa1, ba1, Wo, Wdec);
    k_phase<<<(N_F + 63) / 64, 256, SMEM_PHASE>>>(bdec, Wa2, feat, bo, out);
}

// round 16
// speedup vs baseline: 1.0567x; 1.0036x over previous
#include <cuda_runtime.h>
#include <cuda_fp16.h>
#include <math.h>
#include <stdint.h>

#define N_F 100000
#define N_H 49152
#define NE  400000
#define TT  12
#define HH  64
#define AHD 128
#define SCANB 98
#define ENCB  ((NE + 255) / 256)
#define FILLB ((NE + 255) / 256)
#define HPB   (N_H / 16)             // 3072 blocks, 16 nodes each
#define PACKB 28                     // 28*1024 = 24576 (Wdec) + 4096 (Wa1)
#define IDXCAP 512

__device__ int     g_deg_se[N_F];
__device__ int     g_deg_de[N_H];
__device__ int     g_deg_sd[N_H];
__device__ int     g_deg_dd[N_F];
__device__ float   g_agg[N_H * TT];
__device__ __half2 g_hp[(size_t)TT * N_H * 32];   // (t, n, h/2)
__device__ int     g_off[N_F + 1];
__device__ int     g_cur[N_F];
__device__ int     g_csr[NE];
__device__ unsigned long long g_lb[SCANB];
__device__ float   g_att[2 * AHD + 2];            // u[128], c2[128], k1, k2
__device__ float   g_ba1[AHD];
__device__ float   g_Wo[HH];
__device__ __align__(16) unsigned g_wdp[TT * 2048];  // packed Wdec fp16 pairs
__device__ __align__(16) unsigned g_wap[4096];       // packed Wa1 fp16 pairs

__device__ __forceinline__ float fast_tanh(float x) {
    float y;
    asm("tanh.approx.f32 %0, %1;" : "=f"(y) : "f"(x));
    return y;
}
__device__ __forceinline__ float nan0(float x) {
    x = (x == x) ? x : 0.f;
    return fminf(fmaxf(x, -3.402823466e38f), 3.402823466e38f);
}
__device__ __forceinline__ float lrelu(float x) { return x > 0.f ? x : 0.01f * x; }
__device__ __forceinline__ unsigned packh2(float a, float b) {
    __half2 h = __floats2half2_rn(a, b);
    return *reinterpret_cast<unsigned*>(&h);
}
__device__ __forceinline__ void mma_f16(float& c0, float& c1, float& c2, float& c3,
                                        unsigned a0, unsigned a1, unsigned a2, unsigned a3,
                                        unsigned b0, unsigned b1) {
    asm("mma.sync.aligned.m16n8k16.row.col.f32.f16.f16.f32 "
        "{%0,%1,%2,%3},{%4,%5,%6,%7},{%8,%9},{%0,%1,%2,%3};"
        : "+f"(c0), "+f"(c1), "+f"(c2), "+f"(c3)
        : "r"(a0), "r"(a1), "r"(a2), "r"(a3), "r"(b0), "r"(b1));
}

// ---------------- launch 0: degrees ----------------
__global__ void k_deg(const int* __restrict__ es, const int* __restrict__ ed,
                      const int* __restrict__ ds, const int* __restrict__ dd) {
    int e = blockIdx.x * blockDim.x + threadIdx.x;
    if (e >= NE) return;
    atomicAdd(&g_deg_se[es[e]], 1);
    atomicAdd(&g_deg_de[ed[e]], 1);
    atomicAdd(&g_deg_sd[ds[e]], 1);
    atomicAdd(&g_deg_dd[dd[e]], 1);
}

// ---------------- launch 1: decoupled-lookback scan + encoder scatter ----------------
__global__ void k_enc_scan(const float* __restrict__ feat, const int* __restrict__ es,
                           const int* __restrict__ ed) {
    int tid = threadIdx.x;
    if (blockIdx.x >= SCANB) {
        int e = (blockIdx.x - SCANB) * 256 + tid;
        if (e >= NE) return;
        int s = es[e], d = ed[e];
        float c = rsqrtf(fmaxf((float)g_deg_se[s], 1.f));
        const float4* fp = reinterpret_cast<const float4*>(feat + (size_t)s * 12);
        float4 v0 = fp[0], v1 = fp[1], v2 = fp[2];
        float vv[12] = {v0.x, v0.y, v0.z, v0.w, v1.x, v1.y, v1.z, v1.w, v2.x, v2.y, v2.z, v2.w};
        float* ap = g_agg + (size_t)d * TT;
#pragma unroll
        for (int t = 0; t < 12; t++) atomicAdd(ap + t, nan0(vv[t]) * c);
        return;
    }
    int sb = blockIdx.x;
    int lane = tid & 31, wid = tid >> 5;
    int i0 = sb * 1024 + tid * 4;
    int v0 = 0, v1 = 0, v2 = 0, v3 = 0;
    if (i0 + 3 < N_F) {
        int4 q4 = *reinterpret_cast<const int4*>(&g_deg_dd[i0]);
        v0 = q4.x; v1 = q4.y; v2 = q4.z; v3 = q4.w;
    } else {
        if (i0 < N_F) v0 = g_deg_dd[i0];
        if (i0 + 1 < N_F) v1 = g_deg_dd[i0 + 1];
        if (i0 + 2 < N_F) v2 = g_deg_dd[i0 + 2];
        if (i0 + 3 < N_F) v3 = g_deg_dd[i0 + 3];
    }
    int s = v0 + v1 + v2 + v3;
    int inc = s;
#pragma unroll
    for (int o = 1; o < 32; o <<= 1) {
        int x = __shfl_up_sync(0xffffffffu, inc, o);
        if (lane >= o) inc += x;
    }
    __shared__ int wsum[8], wbase[8], sTotal, sBase;
    if (lane == 31) wsum[wid] = inc;
    __syncthreads();
    if (tid < 8) {
        int x = wsum[tid];
#pragma unroll
        for (int o = 1; o < 8; o <<= 1) {
            int y = __shfl_up_sync(0xffu, x, o);
            if (tid >= o) x += y;
        }
        wbase[tid] = x - wsum[tid];
        if (tid == 7) sTotal = x;
    }
    __syncthreads();
    int texcl = wbase[wid] + inc - s;
    int total = sTotal;
    if (wid == 0) {
        if (sb == 0) {
            if (lane == 0) {
                atomicExch(&g_lb[0], (2ull << 32) | (unsigned)total);
                sBase = 0;
            }
        } else {
            if (lane == 0) atomicExch(&g_lb[sb], (1ull << 32) | (unsigned)total);
            long long run = 0;
            int j = sb - 1;
            bool done = false;
            while (!done) {
                int jj = j - lane;
                unsigned long long tk = 0;
                if (jj >= 0) {
                    do { tk = atomicAdd(&g_lb[jj], 0ull); } while ((unsigned)(tk >> 32) == 0u);
                }
                unsigned incm = __ballot_sync(0xffffffffu, jj >= 0 && (unsigned)(tk >> 32) == 2u);
                int nvalid = min(32, j + 1);
                long long mv;
                if (incm) {
                    int fi = __ffs(incm) - 1;
                    mv = (jj >= 0 && lane <= fi) ? (long long)(unsigned)tk : 0;
                } else {
                    mv = (jj >= 0) ? (long long)(unsigned)tk : 0;
                }
#pragma unroll
                for (int o = 16; o; o >>= 1) mv += __shfl_down_sync(0xffffffffu, mv, o);
                run += __shfl_sync(0xffffffffu, mv, 0);
                if (incm) done = true;
                else {
                    j -= nvalid;
                    if (j < 0) done = true;
                }
            }
            if (lane == 0) {
                atomicExch(&g_lb[sb], (2ull << 32) | (unsigned)(run + total));
                sBase = (int)run;
            }
        }
    }
    __syncthreads();
    int e0 = sBase + texcl;
    if (i0 < N_F)     { g_cur[i0] = e0;         g_off[i0 + 1] = e0 + v0; }
    int e1 = e0 + v0;
    if (i0 + 1 < N_F) { g_cur[i0 + 1] = e1;     g_off[i0 + 2] = e1 + v1; }
    int e2 = e1 + v1;
    if (i0 + 2 < N_F) { g_cur[i0 + 2] = e2;     g_off[i0 + 3] = e2 + v2; }
    int e3 = e2 + v2;
    if (i0 + 3 < N_F) { g_cur[i0 + 3] = e3;     g_off[i0 + 4] = e3 + v3; }
    if (i0 == 0) g_off[0] = 0;
}

// ---------------- launch 2: CSR fill + hproc(16 nodes/blk) + att + weight pre-pack ----------------
__global__ void k_mid(const int* __restrict__ ds, const int* __restrict__ dd,
                      const float* __restrict__ Wenc, const float* __restrict__ benc,
                      const float* __restrict__ Wproc, const float* __restrict__ bproc,
                      const float* __restrict__ Wlin, const float* __restrict__ blin,
                      const float* __restrict__ Wa1, const float* __restrict__ ba1,
                      const float* __restrict__ Wo, const float* __restrict__ Wdec) {
    int tid = threadIdx.x;
    int bid = blockIdx.x;
    if (bid < FILLB) {
        int e = bid * 256 + tid;
        if (e >= NE) return;
        int pos = atomicAdd(&g_cur[dd[e]], 1);
        g_csr[pos] = ds[e];
        return;
    }
    if (bid == FILLB + HPB) {   // att precompute + vector copies
        int j = tid;
        if (j < AHD) {
            float u = 0.f, c = 0.f;
            for (int h = 0; h < HH; h++) {
                float ww = Wa1[h * AHD + j];
                u = fmaf(Wlin[h], ww, u);
                c = fmaf(blin[h], ww, c);
            }
            g_att[j] = u;
            g_att[AHD + j] = c + ba1[j];
            g_ba1[j] = ba1[j];
        }
        if (j < HH) g_Wo[j] = Wo[j];
        if (j == 0) {
            float k1 = 0.f, k2 = 0.f;
            for (int h = 0; h < HH; h++) { k1 = fmaf(Wlin[h], Wo[h], k1); k2 = fmaf(blin[h], Wo[h], k2); }
            g_att[2 * AHD] = k1;
            g_att[2 * AHD + 1] = k2;
        }
        return;
    }
    if (bid > FILLB + HPB) {    // weight pre-pack (28 blocks x 1024 words)
        int pb = bid - (FILLB + HPB + 1);
#pragma unroll
        for (int rep = 0; rep < 4; rep++) {
            int i = pb * 1024 + rep * 256 + tid;
            if (i < TT * 2048) {
                int t = i >> 11, r = i & 2047;
                int k2 = r >> 6, n = r & 63;
                g_wdp[i] = packh2(Wdec[t * 4096 + (2 * k2) * 64 + n],
                                  Wdec[t * 4096 + (2 * k2 + 1) * 64 + n]);
            } else {
                int j = i - TT * 2048;   // < 4096
                int k2 = j >> 7, n = j & 127;
                g_wap[j] = packh2(Wa1[(2 * k2) * 128 + n], Wa1[(2 * k2 + 1) * 128 + n]);
            }
        }
        return;
    }
    // ---- hproc: 16 nodes per block ----
    __shared__ float sWe[TT * HH], sBe[TT * HH], sWp[TT * TT], sBp[TT];
    for (int i = tid; i < TT * HH; i += 256) { sWe[i] = Wenc[i]; sBe[i] = benc[i]; }
    if (tid < TT * TT) sWp[tid] = Wproc[tid];
    if (tid < TT) sBp[tid] = bproc[tid];
    __syncthreads();
    int nb0 = (bid - FILLB) * 16;
    int h = tid & 63;
#pragma unroll 1
    for (int nn = 0; nn < 4; nn++) {
        int n = nb0 + nn * 4 + (tid >> 6);
        float cde = rsqrtf(fmaxf((float)g_deg_de[n], 1.f));
        float csd = rsqrtf(fmaxf((float)g_deg_sd[n], 1.f));
        const float4* ap = reinterpret_cast<const float4*>(g_agg + n * TT);
        float4 a0 = ap[0], a1 = ap[1], a2 = ap[2];
        float av[12] = {a0.x, a0.y, a0.z, a0.w, a1.x, a1.y, a1.z, a1.w, a2.x, a2.y, a2.z, a2.w};
        float he[TT];
#pragma unroll
        for (int t = 0; t < TT; t++)
            he[t] = lrelu(fmaf(av[t] * cde, sWe[t * HH + h], sBe[t * HH + h]));
#pragma unroll
        for (int o = 0; o < TT; o++) {
            float v = sBp[o];
#pragma unroll
            for (int t = 0; t < TT; t++) v = fmaf(he[t], sWp[t * TT + o], v);
            v = fmaxf(v, 0.f) * csd;
            float vhi = __shfl_down_sync(0xffffffffu, v, 1);
            if ((h & 1) == 0)
                g_hp[((size_t)o * N_H + n) * 32 + (h >> 1)] = __floats2half2_rn(v, vhi);
        }
    }
}

// ---------------- launch 3 (PROFILED): fused phase + recurrence (R8-exact) ----------------
#define W_A     0
#define W_WD0   2304
#define W_WD1   4608
#define W_WA    6912
#define W_IDX   11264
#define W_B0    11776
#define W_B1    11840
#define W_BA1   11904
#define W_WA2V  12032
#define W_WO    12160
#define W_SC    12224
#define W_S1O   12992
#define W_SUP   13760
#define W_SC2P  13888
#define W_W2P   14016
#define W_CDD   14144
#define W_TOT   14208
#define SMEM_PHASE (W_TOT * 4)

__global__ void __launch_bounds__(256)
k_phase(const float* __restrict__ bdec, const float* __restrict__ Wa2,
        const float* __restrict__ feat, const float* __restrict__ bo,
        float* __restrict__ out) {
    extern __shared__ unsigned usm[];
    unsigned* uA   = usm + W_A;
    unsigned* sIdx = usm + W_IDX;
    float* fB0  = (float*)(usm + W_B0);
    float* fB1  = (float*)(usm + W_B1);
    float* fBa1 = (float*)(usm + W_BA1);
    float* fWa2 = (float*)(usm + W_WA2V);
    float* fWo  = (float*)(usm + W_WO);
    float* fSc  = (float*)(usm + W_SC);
    float* fS1o = (float*)(usm + W_S1O);
    float* fSuP = (float*)(usm + W_SUP);
    float* fSc2P= (float*)(usm + W_SC2P);
    float* fW2P = (float*)(usm + W_W2P);
    float* fCdd = (float*)(usm + W_CDD);

    int row0 = blockIdx.x * 64;
    int tid = threadIdx.x;
    int w = tid >> 5, lane = tid & 31;

    // once-per-block fills (vectorized copies of pre-packed weights)
    {
        const uint4* wav = reinterpret_cast<const uint4*>(g_wap);
#pragma unroll
        for (int rep = 0; rep < 4; rep++) {
            int i = rep * 256 + tid;          // 1024 uint4
            int k2 = i >> 5, n4 = (i & 31) * 4;
            *reinterpret_cast<uint4*>(&usm[W_WA + k2 * 136 + n4]) = wav[i];
        }
        const uint4* wdv = reinterpret_cast<const uint4*>(g_wdp);
#pragma unroll
        for (int rep = 0; rep < 2; rep++) {
            int i = rep * 256 + tid;          // 512 uint4 (t=0)
            int k2 = i >> 4, n4 = (i & 15) * 4;
            *reinterpret_cast<uint4*>(&usm[W_WD0 + k2 * 72 + n4]) = wdv[i];
        }
    }
    if (tid < 64) {
        fB0[tid] = bdec[tid];
        fWo[tid] = g_Wo[tid];
        int f = row0 + tid;
        fCdd[tid] = (f < N_F) ? rsqrtf(fmaxf((float)g_deg_dd[f], 1.f)) : 0.f;
    }
    if (tid < 128) {
        int p = (tid >> 5) + ((tid & 31) << 2);
        fSuP[p]  = g_att[tid];
        fSc2P[p] = g_att[128 + tid];
        fW2P[p]  = Wa2[tid];
        fBa1[tid] = g_ba1[tid];
        fWa2[tid] = Wa2[tid];
    }
    for (int i = tid; i < 1536; i += 256) fSc[i] = 0.f;   // fSc + fS1o

    // tile edge range; stage CSR as BYTE offsets
    int E0 = g_off[row0];
    int rend = row0 + 64; if (rend > N_F) rend = N_F;
    int ecount = g_off[rend] - E0;
    bool staged = (ecount <= IDXCAP);
    if (staged)
        for (int i = tid; i < ecount; i += 256)
            sIdx[i] = ((unsigned)g_csr[E0 + i]) << 7;

    int bofs[8], len[8];
#pragma unroll
    for (int rr = 0; rr < 8; rr++) {
        int f = row0 + w * 8 + rr;
        if (f < N_F) {
            int bg = g_off[f];
            bofs[rr] = bg - E0;
            len[rr] = g_off[f + 1] - bg;
        } else { bofs[rr] = 0; len[rr] = 0; }
    }
    int maxlen = 0;
#pragma unroll
    for (int rr = 0; rr < 8; rr++) maxlen = max(maxlen, len[rr]);

    int g = lane >> 2, q = lane & 3;
    int r0 = (w & 3) * 16;
    int colsel = w >> 2;

#pragma unroll 1
    for (int t = 0; t < TT; t++) {
        unsigned* uWdC = usm + ((t & 1) ? W_WD1 : W_WD0);
        unsigned* uWdN = usm + ((t & 1) ? W_WD0 : W_WD1);
        float* fBC = (t & 1) ? fB1 : fB0;
        float* fBN = (t & 1) ? fB0 : fB1;

        __syncthreads();
        // ---- gather: half2 accumulate, 32-bit offsets, joint 8-row walk ----
        const char* hbl = (const char*)g_hp + (size_t)t * (N_H * 128) + lane * 4;
        __half2 acc[8];
#pragma unroll
        for (int rr = 0; rr < 8; rr++) acc[rr] = __floats2half2_rn(0.f, 0.f);
        if (staged) {
            for (int s = 0; s < maxlen; s++) {
#pragma unroll
                for (int rr = 0; rr < 8; rr++) {
                    if (s < len[rr]) {
                        unsigned off = sIdx[bofs[rr] + s];
                        acc[rr] = __hadd2(acc[rr], *(const __half2*)(hbl + off));
                    }
                }
            }
        } else {
            for (int s = 0; s < maxlen; s++) {
#pragma unroll
                for (int rr = 0; rr < 8; rr++) {
                    if (s < len[rr]) {
                        unsigned off = ((unsigned)g_csr[E0 + bofs[rr] + s]) << 7;
                        acc[rr] = __hadd2(acc[rr], *(const __half2*)(hbl + off));
                    }
                }
            }
        }
#pragma unroll
        for (int rr = 0; rr < 8; rr++) {
            int r = w * 8 + rr;
            float cd = fCdd[r];
            float2 v = __half22float2(acc[rr]);
            uA[r * 36 + lane] = packh2(v.x * cd, v.y * cd);
        }
        __syncthreads();

        // ---- GEMM1 (fp16): space1 = leaky(A @ Wdec_t + b) ----
        float c1[4][4];
#pragma unroll
        for (int tn = 0; tn < 4; tn++)
#pragma unroll
            for (int i = 0; i < 4; i++) c1[tn][i] = 0.f;
#pragma unroll
        for (int ks = 0; ks < 4; ks++) {
            int kp = ks * 8;
            unsigned va0 = uA[(r0 + g) * 36 + kp + q];
            unsigned va1 = uA[(r0 + g + 8) * 36 + kp + q];
            unsigned va2 = uA[(r0 + g) * 36 + kp + q + 4];
            unsigned va3 = uA[(r0 + g + 8) * 36 + kp + q + 4];
#pragma unroll
            for (int tn = 0; tn < 4; tn++) {
                int nb = colsel * 32 + tn * 8 + g;
                unsigned b0 = uWdC[(kp + q) * 72 + nb];
                unsigned b1 = uWdC[(kp + q + 4) * 72 + nb];
                mma_f16(c1[tn][0], c1[tn][1], c1[tn][2], c1[tn][3], va0, va1, va2, va3, b0, b1);
            }
        }
        __syncthreads();
        // epilogue: bias+leaky -> hA; fused s1o partials from fragments
        __half2* hA = reinterpret_cast<__half2*>(uA);
        float p0 = 0.f, p1 = 0.f;
#pragma unroll
        for (int tn = 0; tn < 4; tn++) {
            int colp = colsel * 16 + tn * 4 + q;
            int col0 = 2 * colp;
            float v00 = lrelu(c1[tn][0] + fBC[col0]);
            float v01 = lrelu(c1[tn][1] + fBC[col0 + 1]);
            float v10 = lrelu(c1[tn][2] + fBC[col0]);
            float v11 = lrelu(c1[tn][3] + fBC[col0 + 1]);
            hA[(r0 + g) * 36 + colp]     = __floats2half2_rn(v00, v01);
            hA[(r0 + g + 8) * 36 + colp] = __floats2half2_rn(v10, v11);
            float w0 = fWo[col0], w1 = fWo[col0 + 1];
            p0 = fmaf(v00, w0, fmaf(v01, w1, p0));
            p1 = fmaf(v10, w0, fmaf(v11, w1, p1));
        }
        p0 += __shfl_down_sync(0xffffffffu, p0, 2, 4);
        p0 += __shfl_down_sync(0xffffffffu, p0, 1, 4);
        p1 += __shfl_down_sync(0xffffffffu, p1, 2, 4);
        p1 += __shfl_down_sync(0xffffffffu, p1, 1, 4);
        if (q == 0) {
            atomicAdd(&fS1o[t * 64 + r0 + g], p0);
            atomicAdd(&fS1o[t * 64 + r0 + g + 8], p1);
        }
        // prefetch next t's packed Wdec + bdec
        if (t + 1 < TT) {
            const uint4* wdv = reinterpret_cast<const uint4*>(g_wdp + (t + 1) * 2048);
#pragma unroll
            for (int rep = 0; rep < 2; rep++) {
                int i = rep * 256 + tid;
                int k2 = i >> 4, n4 = (i & 15) * 4;
                *reinterpret_cast<uint4*>(&uWdN[k2 * 72 + n4]) = wdv[i];
            }
            if (tid < 64) fBN[tid] = bdec[(t + 1) * 64 + tid];
        }
        __syncthreads();

        // ---- GEMM2: z = space1 @ Wa1; score1 = tanh(z+ba1)@Wa2 ----
        float sc0 = 0.f, sc1 = 0.f;
#pragma unroll
        for (int pass = 0; pass < 2; ++pass) {
            float z[4][4];
#pragma unroll
            for (int tn = 0; tn < 4; tn++)
#pragma unroll
                for (int i = 0; i < 4; i++) z[tn][i] = 0.f;
#pragma unroll
            for (int ks = 0; ks < 4; ks++) {
                int kp = ks * 8;
                unsigned va0 = uA[(r0 + g) * 36 + kp + q];
                unsigned va1 = uA[(r0 + g + 8) * 36 + kp + q];
                unsigned va2 = uA[(r0 + g) * 36 + kp + q + 4];
                unsigned va3 = uA[(r0 + g + 8) * 36 + kp + q + 4];
#pragma unroll
                for (int tn = 0; tn < 4; tn++) {
                    int cb = colsel * 64 + pass * 32 + tn * 8 + g;
                    unsigned b0 = usm[W_WA + (kp + q) * 136 + cb];
                    unsigned b1 = usm[W_WA + (kp + q + 4) * 136 + cb];
                    mma_f16(z[tn][0], z[tn][1], z[tn][2], z[tn][3], va0, va1, va2, va3, b0, b1);
                }
            }
#pragma unroll
            for (int tn = 0; tn < 4; tn++) {
                int col0 = colsel * 64 + pass * 32 + tn * 8 + 2 * q;
                sc0 = fmaf(fast_tanh(z[tn][0] + fBa1[col0]),     fWa2[col0],     sc0);
                sc0 = fmaf(fast_tanh(z[tn][1] + fBa1[col0 + 1]), fWa2[col0 + 1], sc0);
                sc1 = fmaf(fast_tanh(z[tn][2] + fBa1[col0]),     fWa2[col0],     sc1);
                sc1 = fmaf(fast_tanh(z[tn][3] + fBa1[col0 + 1]), fWa2[col0 + 1], sc1);
            }
        }
        sc0 += __shfl_down_sync(0xffffffffu, sc0, 2, 4);
        sc0 += __shfl_down_sync(0xffffffffu, sc0, 1, 4);
        sc1 += __shfl_down_sync(0xffffffffu, sc1, 2, 4);
        sc1 += __shfl_down_sync(0xffffffffu, sc1, 1, 4);
        if (q == 0) {
            atomicAdd(&fSc[t * 64 + r0 + g], sc0);
            atomicAdd(&fSc[t * 64 + r0 + g + 8], sc1);
        }
    }
    __syncthreads();

    // ---- fused recurrence: 4 threads per row ----
    int rowi = tid >> 2, sub = tid & 3;
    int f = row0 + rowi;
    float y = 0.f;
    if (f < N_F) y = nan0(feat[(size_t)f * 12 + 11]);
    float k1 = g_att[256], k2v = g_att[257], b0v = bo[0];
#pragma unroll 1
    for (int t = 0; t < TT; t++) {
        float p = 0.f;
#pragma unroll 8
        for (int jj = 0; jj < 32; jj++) {
            int pi = sub + 4 * jj;
            p = fmaf(fast_tanh(fmaf(y, fSuP[pi], fSc2P[pi])), fW2P[pi], p);
        }
        p += __shfl_xor_sync(0xffffffffu, p, 1, 4);
        p += __shfl_xor_sync(0xffffffffu, p, 2, 4);
        float s2 = p;
        float s1 = fSc[t * 64 + rowi];
        float mx = fmaxf(s1, s2);
        float e1 = __expf(s1 - mx), e2 = __expf(s2 - mx);
        float al = e1 / (e1 + e2);
        y = fmaf(al, fS1o[t * 64 + rowi], (1.f - al) * fmaf(y, k1, k2v)) + b0v;
        if (f < N_F && sub == 0) out[(size_t)t * N_F + f] = y;
    }
}

extern "C" void kernel_launch(void* const* d_in, const int* in_sizes, int n_in,
                              void* d_out, int out_size) {
    const float* feat  = (const float*)d_in[0];
    const int*   es    = (const int*)d_in[1];
    const int*   ed    = (const int*)d_in[2];
    const int*   ds    = (const int*)d_in[3];
    const int*   dd    = (const int*)d_in[4];
    const float* Wenc  = (const float*)d_in[5];
    const float* benc  = (const float*)d_in[6];
    const float* Wproc = (const float*)d_in[7];
    const float* bproc = (const float*)d_in[8];
    const float* Wdec  = (const float*)d_in[9];
    const float* bdec  = (const float*)d_in[10];
    const float* Wlin  = (const float*)d_in[11];
    const float* blin  = (const float*)d_in[12];
    const float* Wa1   = (const float*)d_in[13];
    const float* ba1   = (const float*)d_in[14];
    const float* Wa2   = (const float*)d_in[15];
    const float* Wo    = (const float*)d_in[17];
    const float* bo    = (const float*)d_in[18];
    float* out = (float*)d_out;

    cudaFuncSetAttribute(k_phase, cudaFuncAttributeMaxDynamicSharedMemorySize, SMEM_PHASE);

    void *p_se, *p_de, *p_sd, *p_dd, *p_agg, *p_lb;
    cudaGetSymbolAddress(&p_se, g_deg_se);
    cudaGetSymbolAddress(&p_de, g_deg_de);
    cudaGetSymbolAddress(&p_sd, g_deg_sd);
    cudaGetSymbolAddress(&p_dd, g_deg_dd);
    cudaGetSymbolAddress(&p_agg, g_agg);
    cudaGetSymbolAddress(&p_lb, g_lb);
    cudaMemsetAsync(p_se, 0, N_F * sizeof(int));
    cudaMemsetAsync(p_de, 0, N_H * sizeof(int));
    cudaMemsetAsync(p_sd, 0, N_H * sizeof(int));
    cudaMemsetAsync(p_dd, 0, N_F * sizeof(int));
    cudaMemsetAsync(p_agg, 0, N_H * TT * sizeof(float));
    cudaMemsetAsync(p_lb, 0, SCANB * sizeof(unsigned long long));

    k_deg<<<(NE + 255) / 256, 256>>>(es, ed, ds, dd);
    k_enc_scan<<<SCANB + ENCB, 256>>>(feat, es, ed);
    k_mid<<<FILLB + HPB + 1 + PACKB, 256>>>(ds, dd, Wenc, benc, Wproc, bproc,
                                            Wlin, blin, Wa1, ba1, Wo, Wdec);
    k_phase<<<(N_F + 63) / 64, 256, SMEM_PHASE>>>(bdec, Wa2, feat, bo, out);
}